// round 1
// baseline (speedup 1.0000x reference)
#include <cuda_runtime.h>
#include <cuda_fp8.h>
#include <cstdio>
#include <cstdint>

// ============================================================================
// FineGrainedFP8SwiGLUMLP — Round 0 baseline.
//
// Pipeline (exact-product math, matches reference up to fp32 summation order):
//   1) detect_kernel : classify fp8-weight storage (1-byte e4m3 vs fp32)
//   2) fq_x_kernel   : bit-exact per-token/per-128-col fake-quant of x
//   3) gemm_kernel   : gate_out = fq(x) @ dequant(gate_w)^T      (fp32 FFMA)
//   4) gemm_kernel   : up_out   = fq(x) @ dequant(up_w)^T
//   5) combine_fq    : hidden   = fq( silu(gate_out) * up_out )  (in-place)
//   6) gemm_kernel   : out      = hidden @ dequant(down_w)^T
// ============================================================================

namespace {

constexpr int MM = 4096;
constexpr int HH = 4096;
constexpr int II = 14336;
constexpr int QB = 128;
constexpr float FP8_MAX = 448.0f;

// Scratch (allocation-free rule: __device__ globals)
__device__ int   g_flag;                      // 1 = weights stored as fp32, 0 = raw e4m3 bytes
__device__ float g_xfq[(size_t)MM * HH];      // fake-quantized x  (64 MB)
__device__ float g_gate[(size_t)MM * II];     // gate_out, then hidden (224 MB)
__device__ float g_up[(size_t)MM * II];       // up_out             (224 MB)

// ---------------------------------------------------------------------------
__device__ __forceinline__ float loadW(const void* w, size_t idx, int flag) {
    if (flag) {
        return reinterpret_cast<const float*>(w)[idx];
    } else {
        __nv_fp8_e4m3 v;
        v.__x = reinterpret_cast<const uint8_t*>(w)[idx];
        return float(v);
    }
}

// Classify storage of the quantized weight tensor. If values were upconverted
// to fp32, every element is an exact e4m3 value -> low 20 mantissa bits are 0.
// If raw 1-byte e4m3, reinterpreting 4 bytes as fp32 gives arbitrary mantissas.
__global__ void detect_kernel(const unsigned* __restrict__ w) {
    int ok = 1;
    for (int i = threadIdx.x; i < 256; i += 32)
        if (w[i] & 0x000FFFFFu) ok = 0;
    ok = __all_sync(0xffffffffu, ok) ? 1 : 0;
    if (threadIdx.x == 0) {
        g_flag = ok;
        printf("ATHENA dtype flag=%d w0=%08x w1=%08x\n", ok, w[0], w[1]);
    }
}

// ---------------------------------------------------------------------------
// Bit-exact fake quantization of x: one warp per (row, 128-col group).
__global__ void fq_x_kernel(const float* __restrict__ x, float* __restrict__ out,
                            int rows, int cols) {
    int warp = (blockIdx.x * blockDim.x + threadIdx.x) >> 5;
    int lane = threadIdx.x & 31;
    int ng = cols / QB;
    if (warp >= rows * ng) return;
    int row = warp / ng, grp = warp % ng;
    const float* p = x + (size_t)row * cols + grp * QB;
    float v[4];
    float amax = 0.0f;
#pragma unroll
    for (int i = 0; i < 4; i++) {
        v[i] = p[lane + 32 * i];
        amax = fmaxf(amax, fabsf(v[i]));
    }
#pragma unroll
    for (int o = 16; o; o >>= 1)
        amax = fmaxf(amax, __shfl_xor_sync(0xffffffffu, amax, o));
    float scale = fmaxf(amax / FP8_MAX, 1e-12f);
    float* q = out + (size_t)row * cols + grp * QB;
#pragma unroll
    for (int i = 0; i < 4; i++) {
        float t = v[i] / scale;                       // IEEE div, matches jnp
        t = fminf(fmaxf(t, -FP8_MAX), FP8_MAX);
        __nv_fp8_e4m3 f8(t);                          // RN, satfinite
        q[lane + 32 * i] = float(f8) * scale;
    }
}

// ---------------------------------------------------------------------------
// hidden = fake_quant( silu(gate) * up ), in-place into gate buffer.
__global__ void combine_fq_kernel(float* __restrict__ gate, const float* __restrict__ up,
                                  int rows, int cols) {
    int warp = (blockIdx.x * blockDim.x + threadIdx.x) >> 5;
    int lane = threadIdx.x & 31;
    int ng = cols / QB;
    if (warp >= rows * ng) return;
    int row = warp / ng, grp = warp % ng;
    size_t off = (size_t)row * cols + grp * QB;
    float* pg = gate + off;
    const float* pu = up + off;
    float h[4];
    float amax = 0.0f;
#pragma unroll
    for (int i = 0; i < 4; i++) {
        float g = pg[lane + 32 * i];
        float u = pu[lane + 32 * i];
        float s = 1.0f / (1.0f + expf(-g));
        h[i] = g * s * u;
        amax = fmaxf(amax, fabsf(h[i]));
    }
#pragma unroll
    for (int o = 16; o; o >>= 1)
        amax = fmaxf(amax, __shfl_xor_sync(0xffffffffu, amax, o));
    float scale = fmaxf(amax / FP8_MAX, 1e-12f);
#pragma unroll
    for (int i = 0; i < 4; i++) {
        float t = h[i] / scale;
        t = fminf(fmaxf(t, -FP8_MAX), FP8_MAX);
        __nv_fp8_e4m3 f8(t);
        pg[lane + 32 * i] = float(f8) * scale;
    }
}

// ---------------------------------------------------------------------------
// C[Mr,N] = A[Mr,K] @ dequant(W[N,K])^T.   128x128 tile, BK=16, 8x8/thread.
// W scale is per [128-row x 128-K] block: Ws[(n/128)*(K/128) + k/128].
__global__ __launch_bounds__(256) void gemm_kernel(
    const float* __restrict__ A, const void* __restrict__ W,
    const float* __restrict__ Ws, float* __restrict__ C,
    int Mr, int N, int K)
{
    __shared__ float As[16][136];
    __shared__ float Bs[16][136];

    const int flag = g_flag;
    const int bm = blockIdx.y * 128;
    const int bn = blockIdx.x * 128;
    const int tid = threadIdx.x;
    const int tx = tid % 16;          // column tile of 8
    const int ty = tid / 16;          // row tile of 8
    const int kb_count = K >> 7;
    const int nb = bn >> 7;

    const int lj = tid % 16;          // k index inside BK for loads
    const int li = tid / 16;          // base row inside tile for loads

    float acc[8][8] = {};

    for (int kk = 0; kk < K; kk += 16) {
        const float sb = Ws[(size_t)nb * kb_count + (kk >> 7)];
#pragma unroll
        for (int r = 0; r < 8; r++) {
            int i = li + r * 16;
            As[lj][i] = A[(size_t)(bm + i) * K + kk + lj];
        }
#pragma unroll
        for (int r = 0; r < 8; r++) {
            int i = li + r * 16;
            Bs[lj][i] = loadW(W, (size_t)(bn + i) * K + kk + lj, flag) * sb;
        }
        __syncthreads();
#pragma unroll
        for (int j = 0; j < 16; j++) {
            float a[8], b[8];
#pragma unroll
            for (int r = 0; r < 8; r++) a[r] = As[j][ty * 8 + r];
#pragma unroll
            for (int c = 0; c < 8; c++) b[c] = Bs[j][tx * 8 + c];
#pragma unroll
            for (int r = 0; r < 8; r++)
#pragma unroll
                for (int c = 0; c < 8; c++)
                    acc[r][c] = fmaf(a[r], b[c], acc[r][c]);
        }
        __syncthreads();
    }

#pragma unroll
    for (int r = 0; r < 8; r++)
#pragma unroll
        for (int c = 0; c < 8; c++)
            C[(size_t)(bm + ty * 8 + r) * N + bn + tx * 8 + c] = acc[r][c];
}

}  // namespace

// ============================================================================
extern "C" void kernel_launch(void* const* d_in, const int* in_sizes, int n_in,
                              void* d_out, int out_size) {
    const float* x  = (const float*)d_in[0];
    const void*  gw = d_in[1];
    const float* gs = (const float*)d_in[2];
    const void*  uw = d_in[3];
    const float* us = (const float*)d_in[4];
    const void*  dw = d_in[5];
    const float* ds = (const float*)d_in[6];
    float* out = (float*)d_out;

    float *xfq = nullptr, *gg = nullptr, *gu = nullptr;
    cudaGetSymbolAddress((void**)&xfq, g_xfq);
    cudaGetSymbolAddress((void**)&gg,  g_gate);
    cudaGetSymbolAddress((void**)&gu,  g_up);

    // 1) storage-format probe (uniform, deterministic, graph-capturable)
    detect_kernel<<<1, 32>>>((const unsigned*)gw);

    // 2) fake-quant x : 4096 rows x 32 groups, one warp each
    {
        int warps = MM * (HH / QB);
        fq_x_kernel<<<warps / 8, 256>>>(x, xfq, MM, HH);
    }

    // 3) gate GEMM, 4) up GEMM   [4096 x 14336], K = 4096
    {
        dim3 grid(II / 128, MM / 128);
        gemm_kernel<<<grid, 256>>>(xfq, gw, gs, gg, MM, II, HH);
        gemm_kernel<<<grid, 256>>>(xfq, uw, us, gu, MM, II, HH);
    }

    // 5) hidden = fq(silu(gate)*up), in place in g_gate
    {
        int warps = MM * (II / QB);
        combine_fq_kernel<<<warps / 8, 256>>>(gg, gu, MM, II);
    }

    // 6) down GEMM  [4096 x 4096], K = 14336
    {
        dim3 grid(HH / 128, MM / 128);
        gemm_kernel<<<grid, 256>>>(gg, dw, ds, out, MM, HH, II);
    }
}

// round 3
// speedup vs baseline: 10.7571x; 10.7571x over previous
#include <cuda_runtime.h>
#include <cuda_fp8.h>
#include <cuda_bf16.h>
#include <cstdint>

// ============================================================================
// FineGrainedFP8SwiGLUMLP — Round 2: bf16 mma.sync (sm_80-safe ISA) with
// per-128-K fp32 promotion. e4m3 values are exact in bf16; bf16 products are
// exact in the fp32 MMA accumulator -> matches reference to fp32-sum order.
//
//   detect      : classify fp8-weight storage (raw e4m3 bytes vs fp32)
//   convert_w   : weights -> bf16 (exact e4m3 values)
//   fq_x        : x -> bf16-quantized values + per-(row,128grp) fp32 scale
//   gemm_bf16   : C = Aq @ Bq^T, MMA per 128-K block, promote with sA*sW
//   combine_fq  : hidden = fq(silu(gate)*up) -> bf16 + scales
// ============================================================================

namespace {

constexpr int MM = 4096, HH = 4096, II = 14336, QB = 128;
constexpr float FP8_MAX = 448.0f;
constexpr int STAGES = 3;
constexpr int STAGE_B = 65536;                    // 32KB A + 32KB B (bf16 128x128 each)
constexpr int SMEM_SZ = STAGES * STAGE_B;         // 192 KB

// ------------------------------- scratch -----------------------------------
__device__ int           g_flag;
__device__ __nv_bfloat16 g_xb[(size_t)MM * HH];
__device__ float         g_xs[(size_t)MM * (HH / QB)];
__device__ __nv_bfloat16 g_gw[(size_t)II * HH];
__device__ __nv_bfloat16 g_uw[(size_t)II * HH];
__device__ __nv_bfloat16 g_dw[(size_t)HH * II];
__device__ float         g_gate[(size_t)MM * II];
__device__ float         g_up[(size_t)MM * II];
__device__ __nv_bfloat16 g_hb[(size_t)MM * II];
__device__ float         g_hs[(size_t)MM * (II / QB)];

// --------------------------- PTX helpers -----------------------------------
__device__ __forceinline__ uint32_t smem_u32(const void* p) {
    uint32_t a;
    asm("{ .reg .u64 t; cvta.to.shared.u64 t, %1; cvt.u32.u64 %0, t; }" : "=r"(a) : "l"(p));
    return a;
}
__device__ __forceinline__ void cp16(uint32_t dst, const void* src) {
    asm volatile("cp.async.cg.shared.global [%0], [%1], 16;" :: "r"(dst), "l"(src));
}
__device__ __forceinline__ void ldsm4(uint32_t* r, uint32_t a) {
    asm volatile("ldmatrix.sync.aligned.m8n8.x4.shared.b16 {%0,%1,%2,%3}, [%4];"
                 : "=r"(r[0]), "=r"(r[1]), "=r"(r[2]), "=r"(r[3]) : "r"(a));
}
__device__ __forceinline__ void mma_bf16(float* d, const uint32_t* a, uint32_t b0, uint32_t b1) {
    asm volatile(
        "mma.sync.aligned.m16n8k16.row.col.f32.bf16.bf16.f32 "
        "{%0,%1,%2,%3}, {%4,%5,%6,%7}, {%8,%9}, {%0,%1,%2,%3};"
        : "+f"(d[0]), "+f"(d[1]), "+f"(d[2]), "+f"(d[3])
        : "r"(a[0]), "r"(a[1]), "r"(a[2]), "r"(a[3]), "r"(b0), "r"(b1));
}

// e4m3 (possibly fp32-stored) -> exact bf16
__device__ __forceinline__ __nv_bfloat16 f8_to_bf16(uint8_t bits) {
    __nv_fp8_e4m3 v; v.__x = bits;
    return __float2bfloat16(float(v));
}

// ------------------------------ aux kernels --------------------------------
__global__ void detect_kernel(const unsigned* __restrict__ w) {
    int ok = 1;
    for (int i = threadIdx.x; i < 256; i += 32)
        if (w[i] & 0x000FFFFFu) ok = 0;
    ok = __all_sync(0xffffffffu, ok) ? 1 : 0;
    if (threadIdx.x == 0) g_flag = ok;
}

__global__ void convert_w_kernel(const void* __restrict__ w, __nv_bfloat16* __restrict__ out,
                                 size_t n4) {
    size_t i = (size_t)blockIdx.x * blockDim.x + threadIdx.x;
    if (i >= n4) return;
    __nv_bfloat16 o[4];
    if (g_flag) {
        float4 v = reinterpret_cast<const float4*>(w)[i];
        o[0] = __float2bfloat16(float(__nv_fp8_e4m3(v.x)));
        o[1] = __float2bfloat16(float(__nv_fp8_e4m3(v.y)));
        o[2] = __float2bfloat16(float(__nv_fp8_e4m3(v.z)));
        o[3] = __float2bfloat16(float(__nv_fp8_e4m3(v.w)));
    } else {
        uchar4 v = reinterpret_cast<const uchar4*>(w)[i];
        o[0] = f8_to_bf16(v.x); o[1] = f8_to_bf16(v.y);
        o[2] = f8_to_bf16(v.z); o[3] = f8_to_bf16(v.w);
    }
    reinterpret_cast<uint2*>(out)[i] = *reinterpret_cast<uint2*>(o);
}

// x -> bf16 quantized values + scales. One warp per (row, 128-col group).
__global__ void fq_x_kernel(const float* __restrict__ x, __nv_bfloat16* __restrict__ q,
                            float* __restrict__ sc, int cols) {
    int warp = (blockIdx.x * blockDim.x + threadIdx.x) >> 5;
    int lane = threadIdx.x & 31;
    int ng = cols / QB;
    int row = warp / ng, grp = warp % ng;
    size_t off = (size_t)row * cols + grp * QB;
    float4 v = reinterpret_cast<const float4*>(x + off)[lane];
    float amax = fmaxf(fmaxf(fabsf(v.x), fabsf(v.y)), fmaxf(fabsf(v.z), fabsf(v.w)));
#pragma unroll
    for (int o = 16; o; o >>= 1)
        amax = fmaxf(amax, __shfl_xor_sync(0xffffffffu, amax, o));
    float scale = fmaxf(amax / FP8_MAX, 1e-12f);
    __nv_bfloat16 u[4];
    u[0] = __float2bfloat16(float(__nv_fp8_e4m3(fminf(fmaxf(v.x / scale, -FP8_MAX), FP8_MAX))));
    u[1] = __float2bfloat16(float(__nv_fp8_e4m3(fminf(fmaxf(v.y / scale, -FP8_MAX), FP8_MAX))));
    u[2] = __float2bfloat16(float(__nv_fp8_e4m3(fminf(fmaxf(v.z / scale, -FP8_MAX), FP8_MAX))));
    u[3] = __float2bfloat16(float(__nv_fp8_e4m3(fminf(fmaxf(v.w / scale, -FP8_MAX), FP8_MAX))));
    reinterpret_cast<uint2*>(q + off)[lane] = *reinterpret_cast<uint2*>(u);
    if (lane == 0) sc[(size_t)row * ng + grp] = scale;
}

__global__ void combine_fq_kernel(const float* __restrict__ gate, const float* __restrict__ up,
                                  __nv_bfloat16* __restrict__ q, float* __restrict__ sc, int cols) {
    int warp = (blockIdx.x * blockDim.x + threadIdx.x) >> 5;
    int lane = threadIdx.x & 31;
    int ng = cols / QB;
    int row = warp / ng, grp = warp % ng;
    size_t off = (size_t)row * cols + grp * QB;
    float4 g = reinterpret_cast<const float4*>(gate + off)[lane];
    float4 u = reinterpret_cast<const float4*>(up + off)[lane];
    float h[4];
    h[0] = g.x * (1.0f / (1.0f + expf(-g.x))) * u.x;
    h[1] = g.y * (1.0f / (1.0f + expf(-g.y))) * u.y;
    h[2] = g.z * (1.0f / (1.0f + expf(-g.z))) * u.z;
    h[3] = g.w * (1.0f / (1.0f + expf(-g.w))) * u.w;
    float amax = fmaxf(fmaxf(fabsf(h[0]), fabsf(h[1])), fmaxf(fabsf(h[2]), fabsf(h[3])));
#pragma unroll
    for (int o = 16; o; o >>= 1)
        amax = fmaxf(amax, __shfl_xor_sync(0xffffffffu, amax, o));
    float scale = fmaxf(amax / FP8_MAX, 1e-12f);
    __nv_bfloat16 o4[4];
#pragma unroll
    for (int i = 0; i < 4; i++)
        o4[i] = __float2bfloat16(float(__nv_fp8_e4m3(fminf(fmaxf(h[i] / scale, -FP8_MAX), FP8_MAX))));
    reinterpret_cast<uint2*>(q + off)[lane] = *reinterpret_cast<uint2*>(o4);
    if (lane == 0) sc[(size_t)row * ng + grp] = scale;
}

// --------------------------- main GEMM kernel ------------------------------
// C[bm:bm+128, bn:bn+128] += sum_kb sA[m,kb]*sW[nb,kb] * (A128 @ B128^T)
// 16 warps, 32x32 warp tiles, 3-stage cp.async pipeline, chunk = 128 K.
__global__ void __launch_bounds__(512, 1) gemm_bf16_kernel(
    const __nv_bfloat16* __restrict__ A, const __nv_bfloat16* __restrict__ B,
    const float* __restrict__ Asc, const float* __restrict__ Wsc,
    float* __restrict__ C, int N, int K)
{
    extern __shared__ char smem[];
    const uint32_t sb = smem_u32(smem);
    const int tid = threadIdx.x, lane = tid & 31, wid = tid >> 5;
    const int wm = wid >> 2, wn = wid & 3;            // 4x4 warp grid
    const int bm = blockIdx.x * 128, bn = blockIdx.y * 128;
    const int nch = K >> 7;

    // ---- stage loader: 128x128 bf16 A and B, 16B chunks, XOR swizzle ----
    auto load_stage = [&](int s, int c) {
        const uint32_t base = sb + (uint32_t)s * STAGE_B;
#pragma unroll
        for (int i = 0; i < 4; i++) {
            int idx = tid + (i << 9);                 // 0..2047
            int row = idx >> 4, ch = idx & 15;
            uint32_t dst = base + (uint32_t)(row << 8) + (uint32_t)((ch ^ (row & 7)) << 4);
            cp16(dst, A + (size_t)(bm + row) * K + c * 128 + ch * 8);
        }
#pragma unroll
        for (int i = 0; i < 4; i++) {
            int idx = tid + (i << 9);
            int row = idx >> 4, ch = idx & 15;
            uint32_t dst = base + 32768u + (uint32_t)(row << 8) + (uint32_t)((ch ^ (row & 7)) << 4);
            cp16(dst, B + (size_t)(bn + row) * K + c * 128 + ch * 8);
        }
        asm volatile("cp.async.commit_group;");
    };

    float full[2][4][4];
#pragma unroll
    for (int t = 0; t < 2; t++)
#pragma unroll
        for (int j = 0; j < 4; j++)
#pragma unroll
            for (int r = 0; r < 4; r++) full[t][j][r] = 0.0f;

    // prologue: chunks 0..STAGES-2
    for (int c = 0; c < STAGES - 1; c++) load_stage(c, c);

    const float* wsc = Wsc + (size_t)blockIdx.y * nch;

    for (int c = 0; c < nch; c++) {
        asm volatile("cp.async.wait_group %0;" :: "n"(STAGES - 2));
        __syncthreads();

        {   // issue next chunk into the stage freed last iteration
            int cl = c + STAGES - 1;
            if (cl < nch) load_stage(cl % STAGES, cl);
            else asm volatile("cp.async.commit_group;");
        }

        const uint32_t Ab = sb + (uint32_t)(c % STAGES) * STAGE_B;
        const uint32_t Bb = Ab + 32768u;

        float cacc[2][4][4];
#pragma unroll
        for (int t = 0; t < 2; t++)
#pragma unroll
            for (int j = 0; j < 4; j++)
#pragma unroll
                for (int r = 0; r < 4; r++) cacc[t][j][r] = 0.0f;

#pragma unroll
        for (int ks = 0; ks < 8; ks++) {
            uint32_t a[2][4], b[2][4];
#pragma unroll
            for (int t = 0; t < 2; t++) {
                int mrow = wm * 32 + t * 16 + (lane & 15);
                int chn = ((ks << 1) + (lane >> 4)) ^ (mrow & 7);
                ldsm4(a[t], Ab + (uint32_t)(mrow << 8) + (uint32_t)(chn << 4));
            }
#pragma unroll
            for (int p = 0; p < 2; p++) {
                int nrow = wn * 32 + p * 16 + (lane & 15);
                int chn = ((ks << 1) + (lane >> 4)) ^ (nrow & 7);
                ldsm4(b[p], Bb + (uint32_t)(nrow << 8) + (uint32_t)(chn << 4));
            }
#pragma unroll
            for (int t = 0; t < 2; t++)
#pragma unroll
                for (int j = 0; j < 4; j++) {
                    int p = j >> 1, o = j & 1;
                    mma_bf16(cacc[t][j], a[t], b[p][o], b[p][o + 2]);
                }
        }

        // promote this 128-K block with exact fp32 scales
        const float sw = wsc[c];
#pragma unroll
        for (int t = 0; t < 2; t++)
#pragma unroll
            for (int h = 0; h < 2; h++) {
                int row = bm + wm * 32 + t * 16 + h * 8 + (lane >> 2);
                float s = Asc[(size_t)row * nch + c] * sw;
#pragma unroll
                for (int j = 0; j < 4; j++) {
                    full[t][j][2 * h]     = fmaf(s, cacc[t][j][2 * h],     full[t][j][2 * h]);
                    full[t][j][2 * h + 1] = fmaf(s, cacc[t][j][2 * h + 1], full[t][j][2 * h + 1]);
                }
            }
        __syncthreads();
    }

    // epilogue
#pragma unroll
    for (int t = 0; t < 2; t++)
#pragma unroll
        for (int h = 0; h < 2; h++) {
            int row = bm + wm * 32 + t * 16 + h * 8 + (lane >> 2);
#pragma unroll
            for (int j = 0; j < 4; j++) {
                int col = bn + wn * 32 + j * 8 + (lane & 3) * 2;
                float2 v = make_float2(full[t][j][2 * h], full[t][j][2 * h + 1]);
                *reinterpret_cast<float2*>(C + (size_t)row * N + col) = v;
            }
        }
}

}  // namespace

// ============================================================================
extern "C" void kernel_launch(void* const* d_in, const int* in_sizes, int n_in,
                              void* d_out, int out_size) {
    const float* x  = (const float*)d_in[0];
    const void*  gw = d_in[1];
    const float* gs = (const float*)d_in[2];
    const void*  uw = d_in[3];
    const float* us = (const float*)d_in[4];
    const void*  dw = d_in[5];
    const float* ds = (const float*)d_in[6];
    float* out = (float*)d_out;

    __nv_bfloat16 *xb, *gwb, *uwb, *dwb, *hb;
    float *xs, *gate, *up, *hs;
    cudaGetSymbolAddress((void**)&xb,  g_xb);
    cudaGetSymbolAddress((void**)&xs,  g_xs);
    cudaGetSymbolAddress((void**)&gwb, g_gw);
    cudaGetSymbolAddress((void**)&uwb, g_uw);
    cudaGetSymbolAddress((void**)&dwb, g_dw);
    cudaGetSymbolAddress((void**)&gate, g_gate);
    cudaGetSymbolAddress((void**)&up,   g_up);
    cudaGetSymbolAddress((void**)&hb,  g_hb);
    cudaGetSymbolAddress((void**)&hs,  g_hs);

    cudaFuncSetAttribute(gemm_bf16_kernel, cudaFuncAttributeMaxDynamicSharedMemorySize, SMEM_SZ);

    detect_kernel<<<1, 32>>>((const unsigned*)gw);

    {   // weights -> exact bf16
        size_t n4 = (size_t)II * HH / 4;
        int blocks = (int)((n4 + 255) / 256);
        convert_w_kernel<<<blocks, 256>>>(gw, gwb, n4);
        convert_w_kernel<<<blocks, 256>>>(uw, uwb, n4);
        convert_w_kernel<<<blocks, 256>>>(dw, dwb, n4);
    }

    fq_x_kernel<<<MM * (HH / QB) / 8, 256>>>(x, xb, xs, HH);

    gemm_bf16_kernel<<<dim3(MM / 128, II / 128), 512, SMEM_SZ>>>(xb, gwb, xs, gs, gate, II, HH);
    gemm_bf16_kernel<<<dim3(MM / 128, II / 128), 512, SMEM_SZ>>>(xb, uwb, xs, us, up,   II, HH);

    combine_fq_kernel<<<MM * (II / QB) / 8, 256>>>(gate, up, hb, hs, II);

    gemm_bf16_kernel<<<dim3(MM / 128, HH / 128), 512, SMEM_SZ>>>(hb, dwb, hs, ds, out, HH, II);
}